// round 10
// baseline (speedup 1.0000x reference)
#include <cuda_runtime.h>
#include <cstdint>

#define BB 8
#define LL 512
#define CC 6
#define KK 9
#define NTOT (BB*LL)
#define BIGF 1e10f
#define POISON 5e29f
#define REAL_THR_D2 1e20f         // real d2 <= ~3e4, poisoned >= ~4e29

#define THREADS 512
#define CTAS_PER_GRAPH 16
#define NODE_STRIDE 28            // floats per node (112B -> conflict-free LDS.128)
#define SCR_STRIDE 17             // u32 scratch stride per thread (odd -> conflict-free)

// dynamic smem: table 512*28 f32 | scratch 512*17 u32 | sec 512 i32
#define SMEM_FLOATS (LL*NODE_STRIDE + LL*SCR_STRIDE + LL)
#define SMEM_BYTES  (SMEM_FLOATS * 4)

#define F32X2_MUL(o,a,b)   asm("mul.rn.f32x2 %0, %1, %2;"     : "=l"(o) : "l"(a), "l"(b))
#define F32X2_ADD(o,a,b)   asm("add.rn.f32x2 %0, %1, %2;"     : "=l"(o) : "l"(a), "l"(b))
#define F32X2_FMA(o,a,b,c) asm("fma.rn.f32x2 %0, %1, %2, %3;" : "=l"(o) : "l"(a), "l"(b), "l"(c))
#define PACK2(o,f)         asm("mov.b64 %0, {%1, %1};"        : "=l"(o) : "r"(__float_as_uint(f)))
#define UNPACK2(lo,hi,v)   asm("mov.b64 {%0, %1}, %2;"        : "=r"(lo), "=r"(hi) : "l"(v))

// compare-exchange on packed (d2bits<<9 | idx) u64s — lexicographic (key, idx)
#define CE(a,b) { unsigned long long _x=v[a], _y=v[b]; bool _p=_x<_y; v[a]=_p?_x:_y; v[b]=_p?_y:_x; }

// Output layout (float32, reference return order):
//   [0) dknn 36864 | [36864) src | [73728) dst | [110592) valid | [147456) glb 16368 | [163824) seq 16320

// one candidate's distance: 18 packed chains, identical rounding to the passing kernel
#define DIST_BODY(P0,P1,P2,P3,P4,P5,MOUT)                                              \
{                                                                                      \
    float _m = 3.4e38f;                                                                \
    _Pragma("unroll")                                                                  \
    for (int c = 0; c < CC; ++c) {                                                     \
        unsigned long long t0, t1, t2, s0, s1, s2, e0, e1, e2;                         \
        F32X2_MUL(t0, bx2[c], P1.x); F32X2_FMA(t0, bx1[c], P0.y, t0); F32X2_FMA(t0, bx0[c], P0.x, t0); \
        F32X2_MUL(t1, bx2[c], P3.x); F32X2_FMA(t1, bx1[c], P2.y, t1); F32X2_FMA(t1, bx0[c], P2.x, t1); \
        F32X2_MUL(t2, bx2[c], P5.x); F32X2_FMA(t2, bx1[c], P4.y, t2); F32X2_FMA(t2, bx0[c], P4.x, t2); \
        F32X2_ADD(s0, bsq[c], P1.y); F32X2_FMA(e0, neg2, t0, s0);                      \
        F32X2_ADD(s1, bsq[c], P3.y); F32X2_FMA(e1, neg2, t1, s1);                      \
        F32X2_ADD(s2, bsq[c], P5.y); F32X2_FMA(e2, neg2, t2, s2);                      \
        unsigned l0, h0, l1, h1, l2, h2;                                               \
        UNPACK2(l0, h0, e0); UNPACK2(l1, h1, e1); UNPACK2(l2, h2, e2);                 \
        float m01 = fminf(__uint_as_float(l0), __uint_as_float(h0));                   \
        float m23 = fminf(__uint_as_float(l1), __uint_as_float(h1));                   \
        float m45 = fminf(__uint_as_float(l2), __uint_as_float(h2));                   \
        _m = fminf(_m, fminf(fminf(m01, m23), m45));                                   \
    }                                                                                  \
    MOUT = fmaxf(_m, 0.0f);                                                            \
}

extern "C" __global__ void __launch_bounds__(THREADS, 1)
knn_kernel(const float* __restrict__ X, const int* __restrict__ AP,
           const int* __restrict__ S, const int* __restrict__ sec,
           float* __restrict__ out)
{
    extern __shared__ float sX[];
    unsigned* sScr = (unsigned*)(sX + LL*NODE_STRIDE);
    int*      sSec = (int*)(sScr + LL*SCR_STRIDE);

    const int g     = blockIdx.x / CTAS_PER_GRAPH;
    const int part  = blockIdx.x % CTAS_PER_GRAPH;
    const int gbase = g * LL;
    const int tid   = threadIdx.x;

    // ---- structural edges (independent of smem; folded in) ----
    {
        const int GLB_PER = 2*LL - 1, SEQ_PER = 2*(LL - 2);
        const int NG = BB*GLB_PER, NS = BB*SEQ_PER;
        float* gq = out + 4*(size_t)NTOT*KK;
        float* sq = gq + 2*NG;
        int t = blockIdx.x * THREADS + tid;
        if (t < NG) {
            int b = t / GLB_PER, e = t % GLB_PER;
            int srcl = (e < LL) ? 0 : (e - LL + 1);
            int dstl = (e < LL) ? e : 0;
            gq[t]      = (float)(srcl + b*LL);
            gq[NG + t] = (float)(dstl + b*LL);
        } else if (t < NG + NS) {
            int u = t - NG;
            int b = u / SEQ_PER, e = u % SEQ_PER;
            int half = LL - 2;
            int srcl = (e < half) ? (1 + e) : (2 + (e - half));
            int dstl = (e < half) ? (2 + e) : (1 + (e - half));
            sq[u]      = (float)(srcl + b*LL);
            sq[NS + u] = (float)(dstl + b*LL);
        }
    }

    // ---- stage graph table, channel-paired for f32x2 (identical to passing kernel) ----
    {
        int j = tid;
        const float* xp  = X  + (size_t)(gbase + j) * (CC*3);
        const int*   app = AP + (size_t)(gbase + j) * CC;
        bool bos = (S[gbase + j] == 0);
        float xs[CC], ys[CC], zs[CC], ws[CC];
        #pragma unroll
        for (int c = 0; c < CC; ++c) {
            float x = xp[c*3+0], y = xp[c*3+1], z = xp[c*3+2];
            float sq = x*x + y*y + z*z;
            if (bos || app[c] == 0) sq = POISON;
            xs[c] = x; ys[c] = y; zs[c] = z; ws[c] = sq;
        }
        float* base = sX + (size_t)j * NODE_STRIDE;
        #pragma unroll
        for (int dp = 0; dp < 3; ++dp) {
            int c0 = 2*dp, c1 = 2*dp + 1;
            *(float4*)(base + dp*8 + 0) = make_float4(xs[c0], xs[c1], ys[c0], ys[c1]);
            *(float4*)(base + dp*8 + 4) = make_float4(zs[c0], zs[c1], ws[c0], ws[c1]);
        }
        sSec[j] = sec[gbase + j];
    }
    __syncthreads();

    const int warp = tid >> 5, lane = tid & 31;
    const int slot = part * 16 + warp;                // 0..255, 2 rows each

    unsigned long long neg2; PACK2(neg2, -2.0f);

    #pragma unroll 1
    for (int rr = 0; rr < 2; ++rr) {
        const int il = slot * 2 + rr;
        const int ig = gbase + il;

        // row-constant broadcast pairs
        unsigned long long bx0[CC], bx1[CC], bx2[CC], bsq[CC];
        {
            const float* base = sX + (size_t)il * NODE_STRIDE;
            #pragma unroll
            for (int dp = 0; dp < 3; ++dp) {
                float4 a = *(const float4*)(base + dp*8 + 0);
                float4 b = *(const float4*)(base + dp*8 + 4);
                int c0 = 2*dp, c1 = 2*dp + 1;
                PACK2(bx0[c0], a.x); PACK2(bx0[c1], a.y);
                PACK2(bx1[c0], a.z); PACK2(bx1[c1], a.w);
                PACK2(bx2[c0], b.x); PACK2(bx2[c1], b.y);
                PACK2(bsq[c0], b.z); PACK2(bsq[c1], b.w);
            }
        }

        unsigned* scr = sScr + tid * SCR_STRIDE;

        // ---- software-pipelined distance loop: prefetch jt+1 before computing jt ----
        {
            const ulonglong2* nd0 = (const ulonglong2*)(sX + (size_t)lane*NODE_STRIDE);
            ulonglong2 A0 = nd0[0], A1 = nd0[1], A2 = nd0[2],
                       A3 = nd0[3], A4 = nd0[4], A5 = nd0[5];

            #pragma unroll 1
            for (int jt = 0; jt < 16; jt += 2) {
                // prefetch candidate jt+1
                const ulonglong2* ndB =
                    (const ulonglong2*)(sX + (size_t)(((jt+1) << 5) | lane)*NODE_STRIDE);
                ulonglong2 B0 = ndB[0], B1 = ndB[1], B2 = ndB[2],
                           B3 = ndB[3], B4 = ndB[4], B5 = ndB[5];

                float mA; DIST_BODY(A0, A1, A2, A3, A4, A5, mA);
                scr[jt] = __float_as_uint(mA);

                // prefetch candidate jt+2 (wraps to jt=0's data on last iter; unused)
                const ulonglong2* ndA =
                    (const ulonglong2*)(sX + (size_t)((((jt+2) & 15) << 5) | lane)*NODE_STRIDE);
                A0 = ndA[0]; A1 = ndA[1]; A2 = ndA[2];
                A3 = ndA[3]; A4 = ndA[4]; A5 = ndA[5];

                float mB; DIST_BODY(B0, B1, B2, B3, B4, B5, mB);
                scr[jt+1] = __float_as_uint(mB);
            }
        }

        // ---- per-lane selection: load 16 keys, pack (key<<9|j), Batcher sort-16 ----
        unsigned long long v[16];
        #pragma unroll
        for (int t = 0; t < 16; ++t) {
            unsigned kk = scr[t];
            v[t] = (((unsigned long long)kk) << 9) | (unsigned)((t << 5) | lane);
        }
        // Batcher odd-even mergesort, 16 inputs, 63 CEs
        CE(0,1) CE(2,3) CE(4,5) CE(6,7) CE(8,9) CE(10,11) CE(12,13) CE(14,15)
        CE(0,2) CE(1,3) CE(4,6) CE(5,7) CE(8,10) CE(9,11) CE(12,14) CE(13,15)
        CE(1,2) CE(5,6) CE(9,10) CE(13,14)
        CE(0,4) CE(1,5) CE(2,6) CE(3,7) CE(8,12) CE(9,13) CE(10,14) CE(11,15)
        CE(2,4) CE(3,5) CE(10,12) CE(11,13)
        CE(1,2) CE(3,4) CE(5,6) CE(9,10) CE(11,12) CE(13,14)
        CE(0,8) CE(1,9) CE(2,10) CE(3,11) CE(4,12) CE(5,13) CE(6,14) CE(7,15)
        CE(4,8) CE(5,9) CE(6,10) CE(7,11)
        CE(2,4) CE(3,5) CE(6,8) CE(7,9) CE(10,12) CE(11,13)
        CE(1,2) CE(3,4) CE(5,6) CE(7,8) CE(9,10) CE(11,12) CE(13,14)

        // ---- warp merge via redux: 9 rounds, lexicographic (key, idx) min ----
        const int seci = sSec[il];
        #pragma unroll 1
        for (int r = 0; r < KK; ++r) {
            unsigned mykey = (unsigned)(v[0] >> 9);
            unsigned kmin  = __reduce_min_sync(0xffffffffu, mykey);
            unsigned myidx = (unsigned)v[0] & 511u;
            unsigned cand  = (mykey == kmin) ? myidx : 1023u;
            unsigned imin  = __reduce_min_sync(0xffffffffu, cand);
            if (mykey == kmin && myidx == imin) {     // exactly one winner
                float d2v  = __uint_as_float(kmin);
                bool  real = (d2v < REAL_THR_D2);
                float dv   = real ? sqrtf(d2v) : BIGF;
                bool  valid = real && (seci == sSec[imin]);
                size_t o0 = (size_t)ig * KK + r;
                out[o0]                        = dv;
                out[(size_t)NTOT*KK     + o0]  = (float)ig;
                out[2*(size_t)NTOT*KK   + o0]  = valid ? (float)(gbase + (int)imin) : -1.0f;
                out[3*(size_t)NTOT*KK   + o0]  = valid ? 1.0f : 0.0f;
                #pragma unroll
                for (int t = 0; t < 8; ++t) v[t] = v[t+1];   // pop head (winner only)
            }
        }
    }
}

extern "C" void kernel_launch(void* const* d_in, const int* in_sizes, int n_in,
                              void* d_out, int out_size)
{
    const float* X   = (const float*)d_in[0];
    const int*   AP  = (const int*)d_in[1];
    const int*   S   = (const int*)d_in[2];
    const int*   sec = (const int*)d_in[3];
    float* out = (float*)d_out;

    cudaFuncSetAttribute((const void*)knn_kernel,
                         cudaFuncAttributeMaxDynamicSharedMemorySize, SMEM_BYTES);
    knn_kernel<<<BB * CTAS_PER_GRAPH, THREADS, SMEM_BYTES>>>(X, AP, S, sec, out);
}